// round 7
// baseline (speedup 1.0000x reference)
#include <cuda_runtime.h>
#include <cstdint>
#include <math.h>

#define SEQ 4096
#define DIM 1024

// Scratch (allocation-free rule: device globals)
__device__ float g_qkv[SEQ * 3 * DIM];      // [Q | K | V] packed, ld = 3072
__device__ float g_s[(size_t)SEQ * SEQ];    // exp(S) (unnormalized P)
__device__ float g_rinv[SEQ];               // 1 / rowsum

// ---------------------------------------------------------------------------
// PTX helpers (base-target-safe: cp.async + mma.sync only)
// ---------------------------------------------------------------------------
__device__ __forceinline__ uint32_t smem_u32(const void* p) {
    uint32_t a;
    asm("{ .reg .u64 t; cvta.to.shared.u64 t, %1; cvt.u32.u64 %0, t; }" : "=r"(a) : "l"(p));
    return a;
}
__device__ __forceinline__ void cp16(uint32_t s, const void* g) {
    asm volatile("cp.async.cg.shared.global [%0], [%1], 16;" :: "r"(s), "l"(g));
}
__device__ __forceinline__ void cp_commit() {
    asm volatile("cp.async.commit_group;" ::: "memory");
}
__device__ __forceinline__ float round_tf32f(float x) {
    uint32_t y;
    asm("cvt.rna.tf32.f32 %0, %1;" : "=r"(y) : "f"(x));
    return __uint_as_float(y);
}
template <bool CVT>
__device__ __forceinline__ uint32_t frag(float v) {
    if (CVT) {
        uint32_t y;
        asm("cvt.rna.tf32.f32 %0, %1;" : "=r"(y) : "f"(v));
        return y;
    }
    return __float_as_uint(v);
}
__device__ __forceinline__ void mma_tf32(float* c, const uint32_t* a, const uint32_t* b) {
    asm volatile(
        "mma.sync.aligned.m16n8k8.row.col.f32.tf32.tf32.f32 "
        "{%0,%1,%2,%3}, {%4,%5,%6,%7}, {%8,%9}, {%0,%1,%2,%3};"
        : "+f"(c[0]), "+f"(c[1]), "+f"(c[2]), "+f"(c[3])
        : "r"(a[0]), "r"(a[1]), "r"(a[2]), "r"(a[3]), "r"(b[0]), "r"(b[1]));
}

// ---------------------------------------------------------------------------
// tf32 mma.sync GEMM: C[M,N] = epi(scale * A[M,K] * opB)
//   BNN=false: opB = B^T, B row-major [N,K] stride ldb (NT form)
//   BNN=true : opB = B,   B row-major [K,N] stride ldb (NN form)
// A row-major [M,K] stride lda. C stride ldc.
// BM=BN=128, BK=16, 4-stage cp.async (1 sync/iter), 256 threads, 8 warps (2x4),
// 64x32 per warp. Requires M%128==0, N%128==0, K%16==0.
// EPI: 0=none, 1=tf32-round, 2=tf32-round(exp(scale*acc)).
// DIV: multiply output rows by rowinv[r].
// CVT: round fragments to tf32 in-loop (for raw fp32 operands).
// PACK3: B/B2/B3 are three [1024,K] weight blocks; CTA selects by col0.
// ---------------------------------------------------------------------------
#define SW 20                       // A / NT-B: words per 16-float k-row
#define SWB 136                     // NN-B: words per 128-float n-row
#define TILE_W (128 * SW)           // 2560 words (NN B tile: 16*136=2176 fits)
#define NSTG 4
#define SMEM_BYTES (NSTG * 2 * TILE_W * 4)   // 81920

template <int EPI, bool DIV, bool CVT, bool BNN, bool PACK3>
__global__ __launch_bounds__(256, 2)
void gemm_mma(const float* __restrict__ A, const float* __restrict__ B,
              const float* __restrict__ B2, const float* __restrict__ B3,
              float* __restrict__ C, int K, int lda, int ldb, int ldc,
              float scale, const float* __restrict__ rowinv)
{
    extern __shared__ float sm[];
    const int tid  = threadIdx.x;
    const int lane = tid & 31;
    const int wid  = tid >> 5;
    const int gid  = lane >> 2;    // 0..7
    const int tig  = lane & 3;     // 0..3
    const int wm   = (wid & 1) * 64;
    const int wn   = (wid >> 1) * 32;
    const int row0 = blockIdx.y * 128;
    const int col0 = blockIdx.x * 128;

    // PACK3: select weight block by output-column block
    const float* Bp = B;
    int cb = col0;
    if (PACK3) {
        if (col0 >= 2048)      { Bp = B3; cb = col0 - 2048; }
        else if (col0 >= 1024) { Bp = B2; cb = col0 - 1024; }
    }

    const int r_ld = tid >> 2;            // 0..63
    const int g_ld = (tid & 3) * 4;       // k-offset (floats)
    const uint32_t sm0 = smem_u32(sm);

    float acc[4][4][4];
#pragma unroll
    for (int i = 0; i < 4; i++)
#pragma unroll
        for (int j = 0; j < 4; j++)
#pragma unroll
            for (int q = 0; q < 4; q++) acc[i][j][q] = 0.0f;

    const int KT = K >> 4;   // K / 16

    auto issue = [&](int slot, int kt) {
        const uint32_t sa = sm0 + (slot * 2 * TILE_W) * 4;
        const uint32_t sb = sa + TILE_W * 4;
        const float* ga = A + (size_t)(row0 + r_ld) * lda + kt * 16 + g_ld;
        cp16(sa + (r_ld * SW + g_ld) * 4, ga);
        cp16(sa + ((r_ld + 64) * SW + g_ld) * 4, ga + (size_t)64 * lda);
        if (!BNN) {
            const float* gb = Bp + (size_t)(cb + r_ld) * ldb + kt * 16 + g_ld;
            cp16(sb + (r_ld * SW + g_ld) * 4, gb);
            cp16(sb + ((r_ld + 64) * SW + g_ld) * 4, gb + (size_t)64 * ldb);
        } else {
            // B tile [16 k-rows][128 n-cols], row stride SWB words
#pragma unroll
            for (int t = 0; t < 2; t++) {
                int c  = tid + t * 256;           // 0..511
                int kr = c >> 5, nc = (c & 31) * 4;
                cp16(sb + (kr * SWB + nc) * 4,
                     Bp + (size_t)(kt * 16 + kr) * ldb + col0 + nc);
            }
        }
    };

    // prologue: 3 stages in flight
    issue(0, 0); cp_commit();
    issue(1, 1); cp_commit();
    issue(2, 2); cp_commit();

    for (int kt = 0; kt < KT; kt++) {
        asm volatile("cp.async.wait_group 2;" ::: "memory");
        __syncthreads();
        // slot (kt+3)&3 == (kt-1)&3: all warps finished kt-1 before the sync.
        if (kt + 3 < KT) issue((kt + 3) & 3, kt + 3);
        cp_commit();

        const float* Sa = sm + ((kt & 3) * 2) * TILE_W;
        const float* Sb = Sa + TILE_W;
        const float* pa  = Sa + (wm + gid) * SW;     // per-warp A row base
        const float* pb  = Sb + (wn + gid) * SW;     // NT: B row base
        const float* pbn = Sb + wn + gid;            // NN: B col base

#pragma unroll
        for (int ks = 0; ks < 2; ks++) {
            const int kw = ks * 8 + tig;
            uint32_t af[4][4], bf[4][2];
#pragma unroll
            for (int mt = 0; mt < 4; mt++) {
                af[mt][0] = frag<CVT>(pa[(mt * 16) * SW + kw]);
                af[mt][1] = frag<CVT>(pa[(mt * 16 + 8) * SW + kw]);
                af[mt][2] = frag<CVT>(pa[(mt * 16) * SW + kw + 4]);
                af[mt][3] = frag<CVT>(pa[(mt * 16 + 8) * SW + kw + 4]);
            }
#pragma unroll
            for (int nt = 0; nt < 4; nt++) {
                if (!BNN) {
                    bf[nt][0] = frag<CVT>(pb[(nt * 8) * SW + kw]);
                    bf[nt][1] = frag<CVT>(pb[(nt * 8) * SW + kw + 4]);
                } else {
                    bf[nt][0] = frag<CVT>(pbn[kw * SWB + nt * 8]);
                    bf[nt][1] = frag<CVT>(pbn[(kw + 4) * SWB + nt * 8]);
                }
            }
#pragma unroll
            for (int mt = 0; mt < 4; mt++)
#pragma unroll
                for (int nt = 0; nt < 4; nt++)
                    mma_tf32(acc[mt][nt], af[mt], bf[nt]);
        }
    }

    // Epilogue: c0/c1 at (row, 2*tig), c2/c3 at (row+8, 2*tig)
#pragma unroll
    for (int mt = 0; mt < 4; mt++) {
        const int r = row0 + wm + mt * 16 + gid;
        float inv0 = 1.0f, inv1 = 1.0f;
        if (DIV) { inv0 = rowinv[r]; inv1 = rowinv[r + 8]; }
#pragma unroll
        for (int nt = 0; nt < 4; nt++) {
            const int c = col0 + wn + nt * 8 + 2 * tig;
            float o0 = acc[mt][nt][0] * scale, o1 = acc[mt][nt][1] * scale;
            float o2 = acc[mt][nt][2] * scale, o3 = acc[mt][nt][3] * scale;
            if (EPI == 2) {
                o0 = __expf(o0); o1 = __expf(o1);
                o2 = __expf(o2); o3 = __expf(o3);
            }
            if (EPI >= 1) {
                o0 = round_tf32f(o0); o1 = round_tf32f(o1);
                o2 = round_tf32f(o2); o3 = round_tf32f(o3);
            }
            if (DIV) { o0 *= inv0; o1 *= inv0; o2 *= inv1; o3 *= inv1; }
            *(float2*)(C + (size_t)r * ldc + c)       = make_float2(o0, o1);
            *(float2*)(C + (size_t)(r + 8) * ldc + c) = make_float2(o2, o3);
        }
    }
}

// ---------------------------------------------------------------------------
// Row-sum reciprocal: rinv[r] = 1 / sum(P[r, :]).  One block per row.
// ---------------------------------------------------------------------------
__global__ __launch_bounds__(256)
void row_inv(const float* __restrict__ P, float* __restrict__ rinv, int N)
{
    __shared__ float red[32];
    const int tid  = threadIdx.x;
    const int lane = tid & 31;
    const int warp = tid >> 5;
    const float4* row4 = (const float4*)(P + (size_t)blockIdx.x * N);

    float s = 0.0f;
    for (int i = tid; i < N / 4; i += 256) {
        float4 v = row4[i];
        s += (v.x + v.y) + (v.z + v.w);
    }
#pragma unroll
    for (int o = 16; o > 0; o >>= 1)
        s += __shfl_xor_sync(0xffffffffu, s, o);
    if (lane == 0) red[warp] = s;
    __syncthreads();
    if (tid < 32) {
        float v = (tid < 8) ? red[tid] : 0.0f;
#pragma unroll
        for (int o = 4; o > 0; o >>= 1)
            v += __shfl_xor_sync(0xffffffffu, v, o);
        if (tid == 0) rinv[blockIdx.x] = 1.0f / v;
    }
}

// ---------------------------------------------------------------------------
extern "C" void kernel_launch(void* const* d_in, const int* in_sizes, int n_in,
                              void* d_out, int out_size)
{
    const float* x  = (const float*)d_in[0];
    const float* Wq = (const float*)d_in[1];
    const float* Wk = (const float*)d_in[2];
    const float* Wv = (const float*)d_in[3];
    float* out = (float*)d_out;

    float *qkvp, *sp, *rip;
    cudaGetSymbolAddress((void**)&qkvp, g_qkv);
    cudaGetSymbolAddress((void**)&sp,   g_s);
    cudaGetSymbolAddress((void**)&rip,  g_rinv);

    cudaFuncSetAttribute((const void*)gemm_mma<1, false, true,  false, true>,
                         cudaFuncAttributeMaxDynamicSharedMemorySize, SMEM_BYTES);
    cudaFuncSetAttribute((const void*)gemm_mma<2, false, false, false, false>,
                         cudaFuncAttributeMaxDynamicSharedMemorySize, SMEM_BYTES);
    cudaFuncSetAttribute((const void*)gemm_mma<0, true,  false, true,  false>,
                         cudaFuncAttributeMaxDynamicSharedMemorySize, SMEM_BYTES);

    const float scale = 1.0f / 32.0f;  // 1/sqrt(1024)

    // [Q|K|V] = X @ [Wq;Wk;Wv]^T   [4096, 3072]   (in-loop cvt, rounded out)
    gemm_mma<1, false, true, false, true>
        <<<dim3(3 * DIM / 128, SEQ / 128), 256, SMEM_BYTES>>>(
        x, Wq, Wk, Wv, qkvp, DIM, DIM, DIM, 3 * DIM, 1.0f, nullptr);

    // P = exp((Q @ K^T) / 32)   [4096, 4096]   (unnormalized, rounded)
    gemm_mma<2, false, false, false, false>
        <<<dim3(SEQ / 128, SEQ / 128), 256, SMEM_BYTES>>>(
        qkvp, qkvp + DIM, nullptr, nullptr, sp, DIM, 3 * DIM, 3 * DIM, SEQ,
        scale, nullptr);

    // rinv[r] = 1 / rowsum(P)
    row_inv<<<SEQ, 256>>>(sp, rip, SEQ);

    // O = (P @ V) * rinv   [4096, 1024]   (NN: V is [k][n] inside packed QKV)
    gemm_mma<0, true, false, true, false>
        <<<dim3(DIM / 128, SEQ / 128), 256, SMEM_BYTES>>>(
        sp, qkvp + 2 * DIM, nullptr, nullptr, out, SEQ, SEQ, 3 * DIM, DIM,
        1.0f, rip);
}

// round 8
// speedup vs baseline: 1.7452x; 1.7452x over previous
#include <cuda_runtime.h>
#include <cuda_fp16.h>
#include <cstdint>
#include <math.h>

#define SEQ 4096
#define DIM 1024

// Scratch (allocation-free rule: device globals)
__device__ __half g_xh[SEQ * DIM];            // fp16 x
__device__ __half g_wqkh[2 * DIM * DIM];      // fp16 [Wq; Wk] packed
__device__ __half g_wvh[DIM * DIM];           // fp16 Wv
__device__ __half g_qkh[SEQ * 2 * DIM];       // [Q | K] fp16, ld = 2048
__device__ __half g_vth[(size_t)DIM * SEQ];   // V^T fp16 [1024, 4096]
__device__ __half g_ph[(size_t)SEQ * SEQ];    // exp(S) fp16 (unnormalized P)
__device__ float  g_rinv[SEQ];                // 1 / rowsum

// ---------------------------------------------------------------------------
// PTX helpers (base-target-safe: cp.async + mma.sync only)
// ---------------------------------------------------------------------------
__device__ __forceinline__ uint32_t smem_u32(const void* p) {
    uint32_t a;
    asm("{ .reg .u64 t; cvta.to.shared.u64 t, %1; cvt.u32.u64 %0, t; }" : "=r"(a) : "l"(p));
    return a;
}
__device__ __forceinline__ void cp16(uint32_t s, const void* g) {
    asm volatile("cp.async.cg.shared.global [%0], [%1], 16;" :: "r"(s), "l"(g));
}
__device__ __forceinline__ void cp_commit() {
    asm volatile("cp.async.commit_group;" ::: "memory");
}
__device__ __forceinline__ void mma_f16(float* c, const uint32_t* a, const uint32_t* b) {
    asm volatile(
        "mma.sync.aligned.m16n8k16.row.col.f32.f16.f16.f32 "
        "{%0,%1,%2,%3}, {%4,%5,%6,%7}, {%8,%9}, {%0,%1,%2,%3};"
        : "+f"(c[0]), "+f"(c[1]), "+f"(c[2]), "+f"(c[3])
        : "r"(a[0]), "r"(a[1]), "r"(a[2]), "r"(a[3]), "r"(b[0]), "r"(b[1]));
}

// ---------------------------------------------------------------------------
// fp32 -> fp16 conversion
// ---------------------------------------------------------------------------
__global__ __launch_bounds__(256)
void f2h(const float* __restrict__ in, __half* __restrict__ out, int n4)
{
    int i = blockIdx.x * 256 + threadIdx.x;
    if (i < n4) {
        float4 v = ((const float4*)in)[i];
        __half2* o = (__half2*)out + 2 * (size_t)i;
        o[0] = __floats2half2_rn(v.x, v.y);
        o[1] = __floats2half2_rn(v.z, v.w);
    }
}

// ---------------------------------------------------------------------------
// fp16 mma.sync NT GEMM: C[M,N] = epi(scale * A[M,K] * B^T)
// A row-major [M,K] fp16 stride lda; B row-major [N,K] fp16 stride ldb.
// BM=BN=128, BK=32 (fp16), 4-stage cp.async (1 sync/iter), 256 threads,
// 8 warps (2x4), 64x32 per warp, m16n8k16 HMMA, fp32 accumulate.
// Requires M%128==0, N%128==0, K%32==0.
// EPI: 0 = fp32 out, 1 = fp16 out, 2 = fp16 exp(scale*acc) out.
// DIV: multiply output rows by rowinv[r] (EPI=0 path).
// ---------------------------------------------------------------------------
#define SW 20                       // smem words per 32-half row (16 used + 4 pad)
#define TILE_W (128 * SW)           // words per A (or B) tile = 2560
#define NSTG 4
#define SMEM_BYTES (NSTG * 2 * TILE_W * 4)   // 81920

template <int EPI, bool DIV>
__global__ __launch_bounds__(256, 2)
void gemm_h(const __half* __restrict__ A, const __half* __restrict__ B,
            void* __restrict__ Cv, int K, int lda, int ldb, int ldc,
            float scale, const float* __restrict__ rowinv)
{
    extern __shared__ float sm[];
    const int tid  = threadIdx.x;
    const int lane = tid & 31;
    const int wid  = tid >> 5;
    const int gid  = lane >> 2;    // 0..7
    const int tig  = lane & 3;     // 0..3
    const int wm   = (wid & 1) * 64;
    const int wn   = (wid >> 1) * 32;
    const int row0 = blockIdx.y * 128;
    const int col0 = blockIdx.x * 128;

    const uint32_t sm0 = smem_u32(sm);

    float acc[4][4][4];
#pragma unroll
    for (int i = 0; i < 4; i++)
#pragma unroll
        for (int j = 0; j < 4; j++)
#pragma unroll
            for (int q = 0; q < 4; q++) acc[i][j][q] = 0.0f;

    const int KT = K >> 5;   // K / 32

    // per stage: A tile 128 rows x 32 halfs (4 x 16B chunks/row) = 512 chunks,
    // B same; 1024 chunks / 256 threads = 4 per thread (2 A + 2 B).
    auto issue = [&](int slot, int kt) {
        const uint32_t sa = sm0 + (slot * 2 * TILE_W) * 4;
        const uint32_t sb = sa + TILE_W * 4;
        const int kb = kt * 32;
#pragma unroll
        for (int t = 0; t < 2; t++) {
            int idx = tid + t * 256;          // 0..511
            int r = idx >> 2, c = idx & 3;    // row, 16B-chunk
            cp16(sa + (r * SW + c * 4) * 4, A + (size_t)(row0 + r) * lda + kb + c * 8);
            cp16(sb + (r * SW + c * 4) * 4, B + (size_t)(col0 + r) * ldb + kb + c * 8);
        }
    };

    // prologue: 3 stages in flight
    issue(0, 0); cp_commit();
    issue(1, 1); cp_commit();
    issue(2, 2); cp_commit();

    for (int kt = 0; kt < KT; kt++) {
        asm volatile("cp.async.wait_group 2;" ::: "memory");
        __syncthreads();
        // slot (kt+3)&3 == (kt-1)&3: all warps finished kt-1 before the sync.
        if (kt + 3 < KT) issue((kt + 3) & 3, kt + 3);
        cp_commit();

        const uint32_t* Sa = (const uint32_t*)sm + ((kt & 3) * 2) * TILE_W;
        const uint32_t* Sb = Sa + TILE_W;
        const uint32_t* pa = Sa + (wm + gid) * SW;   // per-warp A row base
        const uint32_t* pb = Sb + (wn + gid) * SW;   // per-warp B row base

#pragma unroll
        for (int ks = 0; ks < 2; ks++) {            // two k16 steps per k32
            const int kw = ks * 8 + tig;
            uint32_t af[4][4], bf[4][2];
#pragma unroll
            for (int mt = 0; mt < 4; mt++) {
                af[mt][0] = pa[(mt * 16) * SW + kw];
                af[mt][1] = pa[(mt * 16 + 8) * SW + kw];
                af[mt][2] = pa[(mt * 16) * SW + kw + 4];
                af[mt][3] = pa[(mt * 16 + 8) * SW + kw + 4];
            }
#pragma unroll
            for (int nt = 0; nt < 4; nt++) {
                bf[nt][0] = pb[(nt * 8) * SW + kw];
                bf[nt][1] = pb[(nt * 8) * SW + kw + 4];
            }
#pragma unroll
            for (int mt = 0; mt < 4; mt++)
#pragma unroll
                for (int nt = 0; nt < 4; nt++)
                    mma_f16(acc[mt][nt], af[mt], bf[nt]);
        }
    }

    // Epilogue: c0/c1 at (row, 2*tig), c2/c3 at (row+8, 2*tig)
#pragma unroll
    for (int mt = 0; mt < 4; mt++) {
        const int r = row0 + wm + mt * 16 + gid;
        float inv0 = 1.0f, inv1 = 1.0f;
        if (DIV) { inv0 = rowinv[r]; inv1 = rowinv[r + 8]; }
#pragma unroll
        for (int nt = 0; nt < 4; nt++) {
            const int c = col0 + wn + nt * 8 + 2 * tig;
            float o0 = acc[mt][nt][0] * scale, o1 = acc[mt][nt][1] * scale;
            float o2 = acc[mt][nt][2] * scale, o3 = acc[mt][nt][3] * scale;
            if (EPI == 2) {
                o0 = __expf(o0); o1 = __expf(o1);
                o2 = __expf(o2); o3 = __expf(o3);
            }
            if (EPI == 0) {
                float* C = (float*)Cv;
                if (DIV) { o0 *= inv0; o1 *= inv0; o2 *= inv1; o3 *= inv1; }
                *(float2*)(C + (size_t)r * ldc + c)       = make_float2(o0, o1);
                *(float2*)(C + (size_t)(r + 8) * ldc + c) = make_float2(o2, o3);
            } else {
                __half* C = (__half*)Cv;
                *(__half2*)(C + (size_t)r * ldc + c)       = __floats2half2_rn(o0, o1);
                *(__half2*)(C + (size_t)(r + 8) * ldc + c) = __floats2half2_rn(o2, o3);
            }
        }
    }
}

// ---------------------------------------------------------------------------
// Row-sum reciprocal over fp16 P: rinv[r] = 1 / sum(P[r, :]).
// ---------------------------------------------------------------------------
__global__ __launch_bounds__(256)
void row_inv(const __half* __restrict__ P, float* __restrict__ rinv, int N)
{
    __shared__ float red[32];
    const int tid  = threadIdx.x;
    const int lane = tid & 31;
    const int warp = tid >> 5;
    const __half2* row2 = (const __half2*)(P + (size_t)blockIdx.x * N);

    float s = 0.0f;
    for (int i = tid; i < N / 2; i += 256) {
        float2 f = __half22float2(row2[i]);
        s += f.x + f.y;
    }
#pragma unroll
    for (int o = 16; o > 0; o >>= 1)
        s += __shfl_xor_sync(0xffffffffu, s, o);
    if (lane == 0) red[warp] = s;
    __syncthreads();
    if (tid < 32) {
        float v = (tid < 8) ? red[tid] : 0.0f;
#pragma unroll
        for (int o = 4; o > 0; o >>= 1)
            v += __shfl_xor_sync(0xffffffffu, v, o);
        if (tid == 0) rinv[blockIdx.x] = 1.0f / v;
    }
}

// ---------------------------------------------------------------------------
extern "C" void kernel_launch(void* const* d_in, const int* in_sizes, int n_in,
                              void* d_out, int out_size)
{
    const float* x  = (const float*)d_in[0];
    const float* Wq = (const float*)d_in[1];
    const float* Wk = (const float*)d_in[2];
    const float* Wv = (const float*)d_in[3];
    float* out = (float*)d_out;

    __half *xh, *wqkh, *wvh, *qkh, *vth, *ph;
    float *rip;
    cudaGetSymbolAddress((void**)&xh,   g_xh);
    cudaGetSymbolAddress((void**)&wqkh, g_wqkh);
    cudaGetSymbolAddress((void**)&wvh,  g_wvh);
    cudaGetSymbolAddress((void**)&qkh,  g_qkh);
    cudaGetSymbolAddress((void**)&vth,  g_vth);
    cudaGetSymbolAddress((void**)&ph,   g_ph);
    cudaGetSymbolAddress((void**)&rip,  g_rinv);

    cudaFuncSetAttribute((const void*)gemm_h<1, false>,
                         cudaFuncAttributeMaxDynamicSharedMemorySize, SMEM_BYTES);
    cudaFuncSetAttribute((const void*)gemm_h<2, false>,
                         cudaFuncAttributeMaxDynamicSharedMemorySize, SMEM_BYTES);
    cudaFuncSetAttribute((const void*)gemm_h<0, true>,
                         cudaFuncAttributeMaxDynamicSharedMemorySize, SMEM_BYTES);

    const float scale = 1.0f / 32.0f;  // 1/sqrt(1024)

    // fp32 -> fp16 conversion ([Wq;Wk] packed during conversion)
    f2h<<<SEQ * DIM / 1024, 256>>>(x,  xh,   SEQ * DIM / 4);
    f2h<<<DIM * DIM / 1024, 256>>>(Wq, wqkh, DIM * DIM / 4);
    f2h<<<DIM * DIM / 1024, 256>>>(Wk, wqkh + DIM * DIM, DIM * DIM / 4);
    f2h<<<DIM * DIM / 1024, 256>>>(Wv, wvh,  DIM * DIM / 4);

    // [Q|K] = X @ [Wq;Wk]^T   [4096, 2048] fp16
    gemm_h<1, false><<<dim3(2 * DIM / 128, SEQ / 128), 256, SMEM_BYTES>>>(
        xh, wqkh, qkh, DIM, DIM, DIM, 2 * DIM, 1.0f, nullptr);

    // V^T = Wv @ X^T   [1024, 4096] fp16
    gemm_h<1, false><<<dim3(SEQ / 128, DIM / 128), 256, SMEM_BYTES>>>(
        wvh, xh, vth, DIM, DIM, DIM, SEQ, 1.0f, nullptr);

    // P = exp((Q @ K^T) / 32)   [4096, 4096] fp16 (unnormalized)
    gemm_h<2, false><<<dim3(SEQ / 128, SEQ / 128), 256, SMEM_BYTES>>>(
        qkh, qkh + DIM, ph, DIM, 2 * DIM, 2 * DIM, SEQ, scale, nullptr);

    // rinv[r] = 1 / rowsum(P)
    row_inv<<<SEQ, 256>>>(ph, rip, SEQ);

    // O = (P @ (V^T)^T) * rinv   [4096, 1024] fp32
    gemm_h<0, true><<<dim3(DIM / 128, SEQ / 128), 256, SMEM_BYTES>>>(
        ph, vth, out, SEQ, SEQ, SEQ, DIM, 1.0f, rip);
}

// round 9
// speedup vs baseline: 2.0275x; 1.1617x over previous
#include <cuda_runtime.h>
#include <cuda_fp16.h>
#include <cstdint>
#include <math.h>

#define SEQ 4096
#define DIM 1024

// Scratch (allocation-free rule: device globals)
__device__ __half g_xh[SEQ * DIM];            // fp16 x
__device__ __half g_wqkh[2 * DIM * DIM];      // fp16 [Wq; Wk] packed
__device__ __half g_wvh[DIM * DIM];           // fp16 Wv
__device__ __half g_qkh[SEQ * 2 * DIM];       // [Q | K] fp16, ld = 2048
__device__ __half g_vth[(size_t)DIM * SEQ];   // V^T fp16 [1024, 4096]
__device__ __half g_ph[(size_t)SEQ * SEQ];    // exp(S) fp16 (unnormalized P)
__device__ float  g_rinv[SEQ];                // 1 / rowsum

// ---------------------------------------------------------------------------
// PTX helpers (base-target-safe: cp.async + mma.sync + ldmatrix only)
// ---------------------------------------------------------------------------
__device__ __forceinline__ uint32_t smem_u32(const void* p) {
    uint32_t a;
    asm("{ .reg .u64 t; cvta.to.shared.u64 t, %1; cvt.u32.u64 %0, t; }" : "=r"(a) : "l"(p));
    return a;
}
__device__ __forceinline__ void cp16(uint32_t s, const void* g) {
    asm volatile("cp.async.cg.shared.global [%0], [%1], 16;" :: "r"(s), "l"(g));
}
__device__ __forceinline__ void cp_commit() {
    asm volatile("cp.async.commit_group;" ::: "memory");
}
__device__ __forceinline__ void ldmx4(uint32_t* r, uint32_t addr) {
    asm volatile("ldmatrix.sync.aligned.m8n8.x4.shared.b16 {%0,%1,%2,%3}, [%4];"
        : "=r"(r[0]), "=r"(r[1]), "=r"(r[2]), "=r"(r[3]) : "r"(addr));
}
__device__ __forceinline__ void mma_f16(float* c, const uint32_t* a, const uint32_t* b) {
    asm volatile(
        "mma.sync.aligned.m16n8k16.row.col.f32.f16.f16.f32 "
        "{%0,%1,%2,%3}, {%4,%5,%6,%7}, {%8,%9}, {%0,%1,%2,%3};"
        : "+f"(c[0]), "+f"(c[1]), "+f"(c[2]), "+f"(c[3])
        : "r"(a[0]), "r"(a[1]), "r"(a[2]), "r"(a[3]), "r"(b[0]), "r"(b[1]));
}

// ---------------------------------------------------------------------------
// fp32 -> fp16 conversion
// ---------------------------------------------------------------------------
__global__ __launch_bounds__(256)
void f2h(const float* __restrict__ in, __half* __restrict__ out, int n4)
{
    int i = blockIdx.x * 256 + threadIdx.x;
    if (i < n4) {
        float4 v = ((const float4*)in)[i];
        __half2* o = (__half2*)out + 2 * (size_t)i;
        o[0] = __floats2half2_rn(v.x, v.y);
        o[1] = __floats2half2_rn(v.z, v.w);
    }
}

// ---------------------------------------------------------------------------
// fp16 mma.sync NT GEMM: C[M,N] = epi(scale * A[M,K] * B^T)
// A row-major [M,K] fp16 stride lda; B row-major [N,K] fp16 stride ldb.
// BM=BN=128, BK=32 (fp16), 4-stage cp.async (1 sync/iter), 256 threads,
// 8 warps (2x4), 64x32 per warp, ldmatrix.x4 fragments, m16n8k16 HMMA,
// fp32 accumulate. Requires M%128==0, N%128==0, K%32==0.
// EPI: 0 = fp32 out, 1 = fp16 out, 2 = fp16 exp(scale*acc) out.
// DIV: multiply output rows by rowinv[r] (EPI=0 path).
// ---------------------------------------------------------------------------
#define SW 20                       // smem words per 32-half row (16 used + 4 pad)
#define TILE_W (128 * SW)           // words per A (or B) tile = 2560
#define NSTG 4
#define SMEM_BYTES (NSTG * 2 * TILE_W * 4)   // 81920

template <int EPI, bool DIV>
__global__ __launch_bounds__(256, 2)
void gemm_h(const __half* __restrict__ A, const __half* __restrict__ B,
            void* __restrict__ Cv, int K, int lda, int ldb, int ldc,
            float scale, const float* __restrict__ rowinv)
{
    extern __shared__ float sm[];
    const int tid  = threadIdx.x;
    const int lane = tid & 31;
    const int wid  = tid >> 5;
    const int gid  = lane >> 2;    // 0..7
    const int tig  = lane & 3;     // 0..3
    const int wm   = (wid & 1) * 64;
    const int wn   = (wid >> 1) * 32;
    const int row0 = blockIdx.y * 128;
    const int col0 = blockIdx.x * 128;

    const uint32_t sm0 = smem_u32(sm);

    // ldmatrix per-lane address offsets (bytes), within a stage
    const int mat = lane >> 3;     // 0..3
    const int rim = lane & 7;      // row in 8x8 matrix
    uint32_t aOff[4], bOff[2];
#pragma unroll
    for (int mt = 0; mt < 4; mt++)  // A m16 tile: row += (mat&1)*8, kw += (mat>>1)*4
        aOff[mt] = (uint32_t)(((wm + mt * 16 + (mat & 1) * 8 + rim) * SW
                               + (mat >> 1) * 4) * 4);
#pragma unroll
    for (int p = 0; p < 2; p++)     // B nt-pair: row += (mat>>1)*8, kw += (mat&1)*4
        bOff[p] = (uint32_t)((TILE_W + (wn + p * 16 + (mat >> 1) * 8 + rim) * SW
                               + (mat & 1) * 4) * 4);

    float acc[4][4][4];
#pragma unroll
    for (int i = 0; i < 4; i++)
#pragma unroll
        for (int j = 0; j < 4; j++)
#pragma unroll
            for (int q = 0; q < 4; q++) acc[i][j][q] = 0.0f;

    const int KT = K >> 5;   // K / 32

    // per stage: A tile 128 rows x 32 halfs (4 x 16B chunks/row) = 512 chunks,
    // B same; 1024 chunks / 256 threads = 4 per thread (2 A + 2 B).
    auto issue = [&](int slot, int kt) {
        const uint32_t sa = sm0 + (slot * 2 * TILE_W) * 4;
        const uint32_t sb = sa + TILE_W * 4;
        const int kb = kt * 32;
#pragma unroll
        for (int t = 0; t < 2; t++) {
            int idx = tid + t * 256;          // 0..511
            int r = idx >> 2, c = idx & 3;    // row, 16B-chunk
            cp16(sa + (r * SW + c * 4) * 4, A + (size_t)(row0 + r) * lda + kb + c * 8);
            cp16(sb + (r * SW + c * 4) * 4, B + (size_t)(col0 + r) * ldb + kb + c * 8);
        }
    };

    // prologue: 3 stages in flight
    issue(0, 0); cp_commit();
    issue(1, 1); cp_commit();
    issue(2, 2); cp_commit();

    for (int kt = 0; kt < KT; kt++) {
        asm volatile("cp.async.wait_group 2;" ::: "memory");
        __syncthreads();
        // slot (kt+3)&3 == (kt-1)&3: all warps finished kt-1 before the sync.
        if (kt + 3 < KT) issue((kt + 3) & 3, kt + 3);
        cp_commit();

        const uint32_t stg = sm0 + ((kt & 3) * 2 * TILE_W) * 4;

#pragma unroll
        for (int ks = 0; ks < 2; ks++) {            // two k16 steps per k32
            const uint32_t kb = stg + ks * 32;      // ks*8 words = 32 bytes
            uint32_t af[4][4], bq[2][4];
#pragma unroll
            for (int mt = 0; mt < 4; mt++) ldmx4(af[mt], kb + aOff[mt]);
#pragma unroll
            for (int p = 0; p < 2; p++)    ldmx4(bq[p], kb + bOff[p]);
#pragma unroll
            for (int mt = 0; mt < 4; mt++)
#pragma unroll
                for (int nt = 0; nt < 4; nt++)
                    mma_f16(acc[mt][nt], af[mt], &bq[nt >> 1][(nt & 1) * 2]);
        }
    }

    // Epilogue: c0/c1 at (row, 2*tig), c2/c3 at (row+8, 2*tig)
#pragma unroll
    for (int mt = 0; mt < 4; mt++) {
        const int r = row0 + wm + mt * 16 + gid;
        float inv0 = 1.0f, inv1 = 1.0f;
        if (DIV) { inv0 = rowinv[r]; inv1 = rowinv[r + 8]; }
#pragma unroll
        for (int nt = 0; nt < 4; nt++) {
            const int c = col0 + wn + nt * 8 + 2 * tig;
            float o0 = acc[mt][nt][0] * scale, o1 = acc[mt][nt][1] * scale;
            float o2 = acc[mt][nt][2] * scale, o3 = acc[mt][nt][3] * scale;
            if (EPI == 2) {
                o0 = __expf(o0); o1 = __expf(o1);
                o2 = __expf(o2); o3 = __expf(o3);
            }
            if (EPI == 0) {
                float* C = (float*)Cv;
                if (DIV) { o0 *= inv0; o1 *= inv0; o2 *= inv1; o3 *= inv1; }
                *(float2*)(C + (size_t)r * ldc + c)       = make_float2(o0, o1);
                *(float2*)(C + (size_t)(r + 8) * ldc + c) = make_float2(o2, o3);
            } else {
                __half* C = (__half*)Cv;
                *(__half2*)(C + (size_t)r * ldc + c)       = __floats2half2_rn(o0, o1);
                *(__half2*)(C + (size_t)(r + 8) * ldc + c) = __floats2half2_rn(o2, o3);
            }
        }
    }
}

// ---------------------------------------------------------------------------
// Row-sum reciprocal over fp16 P: rinv[r] = 1 / sum(P[r, :]).
// ---------------------------------------------------------------------------
__global__ __launch_bounds__(256)
void row_inv(const __half* __restrict__ P, float* __restrict__ rinv, int N)
{
    __shared__ float red[32];
    const int tid  = threadIdx.x;
    const int lane = tid & 31;
    const int warp = tid >> 5;
    const __half2* row2 = (const __half2*)(P + (size_t)blockIdx.x * N);

    float s = 0.0f;
    for (int i = tid; i < N / 2; i += 256) {
        float2 f = __half22float2(row2[i]);
        s += f.x + f.y;
    }
#pragma unroll
    for (int o = 16; o > 0; o >>= 1)
        s += __shfl_xor_sync(0xffffffffu, s, o);
    if (lane == 0) red[warp] = s;
    __syncthreads();
    if (tid < 32) {
        float v = (tid < 8) ? red[tid] : 0.0f;
#pragma unroll
        for (int o = 4; o > 0; o >>= 1)
            v += __shfl_xor_sync(0xffffffffu, v, o);
        if (tid == 0) rinv[blockIdx.x] = 1.0f / v;
    }
}

// ---------------------------------------------------------------------------
extern "C" void kernel_launch(void* const* d_in, const int* in_sizes, int n_in,
                              void* d_out, int out_size)
{
    const float* x  = (const float*)d_in[0];
    const float* Wq = (const float*)d_in[1];
    const float* Wk = (const float*)d_in[2];
    const float* Wv = (const float*)d_in[3];
    float* out = (float*)d_out;

    __half *xh, *wqkh, *wvh, *qkh, *vth, *ph;
    float *rip;
    cudaGetSymbolAddress((void**)&xh,   g_xh);
    cudaGetSymbolAddress((void**)&wqkh, g_wqkh);
    cudaGetSymbolAddress((void**)&wvh,  g_wvh);
    cudaGetSymbolAddress((void**)&qkh,  g_qkh);
    cudaGetSymbolAddress((void**)&vth,  g_vth);
    cudaGetSymbolAddress((void**)&ph,   g_ph);
    cudaGetSymbolAddress((void**)&rip,  g_rinv);

    cudaFuncSetAttribute((const void*)gemm_h<1, false>,
                         cudaFuncAttributeMaxDynamicSharedMemorySize, SMEM_BYTES);
    cudaFuncSetAttribute((const void*)gemm_h<2, false>,
                         cudaFuncAttributeMaxDynamicSharedMemorySize, SMEM_BYTES);
    cudaFuncSetAttribute((const void*)gemm_h<0, true>,
                         cudaFuncAttributeMaxDynamicSharedMemorySize, SMEM_BYTES);

    const float scale = 1.0f / 32.0f;  // 1/sqrt(1024)

    // fp32 -> fp16 conversion ([Wq;Wk] packed during conversion)
    f2h<<<SEQ * DIM / 1024, 256>>>(x,  xh,   SEQ * DIM / 4);
    f2h<<<DIM * DIM / 1024, 256>>>(Wq, wqkh, DIM * DIM / 4);
    f2h<<<DIM * DIM / 1024, 256>>>(Wk, wqkh + DIM * DIM, DIM * DIM / 4);
    f2h<<<DIM * DIM / 1024, 256>>>(Wv, wvh,  DIM * DIM / 4);

    // [Q|K] = X @ [Wq;Wk]^T   [4096, 2048] fp16
    gemm_h<1, false><<<dim3(2 * DIM / 128, SEQ / 128), 256, SMEM_BYTES>>>(
        xh, wqkh, qkh, DIM, DIM, DIM, 2 * DIM, 1.0f, nullptr);

    // V^T = Wv @ X^T   [1024, 4096] fp16
    gemm_h<1, false><<<dim3(SEQ / 128, DIM / 128), 256, SMEM_BYTES>>>(
        wvh, xh, vth, DIM, DIM, DIM, SEQ, 1.0f, nullptr);

    // P = exp((Q @ K^T) / 32)   [4096, 4096] fp16 (unnormalized)
    gemm_h<2, false><<<dim3(SEQ / 128, SEQ / 128), 256, SMEM_BYTES>>>(
        qkh, qkh + DIM, ph, DIM, 2 * DIM, 2 * DIM, SEQ, scale, nullptr);

    // rinv[r] = 1 / rowsum(P)
    row_inv<<<SEQ, 256>>>(ph, rip, SEQ);

    // O = (P @ (V^T)^T) * rinv   [4096, 1024] fp32
    gemm_h<0, true><<<dim3(DIM / 128, SEQ / 128), 256, SMEM_BYTES>>>(
        ph, vth, out, SEQ, SEQ, SEQ, DIM, 1.0f, rip);
}

// round 10
// speedup vs baseline: 2.3832x; 1.1755x over previous
#include <cuda_runtime.h>
#include <cuda_fp16.h>
#include <cstdint>
#include <math.h>

#define SEQ 4096
#define DIM 1024

// Scratch (allocation-free rule: device globals)
__device__ __half g_xh[SEQ * DIM];            // fp16 x
__device__ __half g_wqkh[2 * DIM * DIM];      // fp16 [Wq; Wk] packed
__device__ __half g_wvh[DIM * DIM];           // fp16 Wv
__device__ __half g_qkh[SEQ * 2 * DIM];       // [Q | K] fp16, ld = 2048
__device__ __half g_vth[(size_t)DIM * SEQ];   // V^T fp16 [1024, 4096]
__device__ __half g_ph[(size_t)SEQ * SEQ];    // exp(S) fp16 (unnormalized P)
__device__ float  g_rsum[SEQ];                // rowsum of P (atomic accum)

// ---------------------------------------------------------------------------
// PTX helpers (base-target-safe: cp.async + mma.sync + ldmatrix only)
// ---------------------------------------------------------------------------
__device__ __forceinline__ uint32_t smem_u32(const void* p) {
    uint32_t a;
    asm("{ .reg .u64 t; cvta.to.shared.u64 t, %1; cvt.u32.u64 %0, t; }" : "=r"(a) : "l"(p));
    return a;
}
__device__ __forceinline__ void cp16(uint32_t s, const void* g) {
    asm volatile("cp.async.cg.shared.global [%0], [%1], 16;" :: "r"(s), "l"(g));
}
__device__ __forceinline__ void cp_commit() {
    asm volatile("cp.async.commit_group;" ::: "memory");
}
__device__ __forceinline__ void ldmx4(uint32_t* r, uint32_t addr) {
    asm volatile("ldmatrix.sync.aligned.m8n8.x4.shared.b16 {%0,%1,%2,%3}, [%4];"
        : "=r"(r[0]), "=r"(r[1]), "=r"(r[2]), "=r"(r[3]) : "r"(addr));
}
__device__ __forceinline__ void mma_f16(float* c, const uint32_t* a, const uint32_t* b) {
    asm volatile(
        "mma.sync.aligned.m16n8k16.row.col.f32.f16.f16.f32 "
        "{%0,%1,%2,%3}, {%4,%5,%6,%7}, {%8,%9}, {%0,%1,%2,%3};"
        : "+f"(c[0]), "+f"(c[1]), "+f"(c[2]), "+f"(c[3])
        : "r"(a[0]), "r"(a[1]), "r"(a[2]), "r"(a[3]), "r"(b[0]), "r"(b[1]));
}

// ---------------------------------------------------------------------------
// Merged fp32 -> fp16 conversion of x, Wq, Wk, Wv (one launch)
// ---------------------------------------------------------------------------
#define XN4   (SEQ * DIM / 4)      // 1048576
#define WN4   (DIM * DIM / 4)      // 262144
__global__ __launch_bounds__(256)
void cvt_all(const float* __restrict__ x,  const float* __restrict__ Wq,
             const float* __restrict__ Wk, const float* __restrict__ Wv,
             __half* __restrict__ xh, __half* __restrict__ wqkh,
             __half* __restrict__ wvh)
{
    int i = blockIdx.x * 256 + threadIdx.x;
    const float* src;
    __half* dst;
    int off;
    if (i < XN4)                 { src = x;  dst = xh;   off = i; }
    else if (i < XN4 + WN4)      { src = Wq; dst = wqkh; off = i - XN4; }
    else if (i < XN4 + 2 * WN4)  { src = Wk; dst = wqkh + DIM * DIM; off = i - XN4 - WN4; }
    else if (i < XN4 + 3 * WN4)  { src = Wv; dst = wvh;  off = i - XN4 - 2 * WN4; }
    else return;
    float4 v = ((const float4*)src)[off];
    __half2* o = (__half2*)dst + 2 * (size_t)off;
    o[0] = __floats2half2_rn(v.x, v.y);
    o[1] = __floats2half2_rn(v.z, v.w);
}

__global__ __launch_bounds__(256)
void zero_rsum(float* __restrict__ rs)
{
    int i = blockIdx.x * 256 + threadIdx.x;
    if (i < SEQ) rs[i] = 0.0f;
}

// ---------------------------------------------------------------------------
// fp16 mma.sync NT GEMM: C[M,N] = epi(scale * A[M,K] * B^T)
// A row-major [M,K] fp16 stride lda; B row-major [N,K] fp16 stride ldb.
// BM=BN=128, BK=32, 4-stage cp.async (1 sync/iter), 128 threads, 4 warps (2x2),
// 64x64 per warp, ldmatrix.x4 fragments, m16n8k16 HMMA, fp32 accumulate.
// 2 CTAs/SM. Requires M%128==0, N%128==0, K%32==0.
// EPI: 0 = fp32 out, 1 = fp16 out, 2 = fp16 exp(scale*acc) out + row-sum atomics.
// DIV: multiply output rows by 1/rsum[r] (EPI=0 path).
// ---------------------------------------------------------------------------
#define SW 20                       // smem words per 32-half row (16 used + 4 pad)
#define TILE_W (128 * SW)           // words per A (or B) tile = 2560
#define NSTG 4
#define SMEM_BYTES (NSTG * 2 * TILE_W * 4)   // 81920

template <int EPI, bool DIV>
__global__ __launch_bounds__(128, 2)
void gemm_h(const __half* __restrict__ A, const __half* __restrict__ B,
            void* __restrict__ Cv, int K, int lda, int ldb, int ldc,
            float scale, float* __restrict__ rsum)
{
    extern __shared__ float sm[];
    const int tid  = threadIdx.x;
    const int lane = tid & 31;
    const int wid  = tid >> 5;     // 0..3
    const int gid  = lane >> 2;    // 0..7
    const int tig  = lane & 3;     // 0..3
    const int wm   = (wid & 1) * 64;
    const int wn   = (wid >> 1) * 64;
    const int row0 = blockIdx.y * 128;
    const int col0 = blockIdx.x * 128;

    const uint32_t sm0 = smem_u32(sm);

    // ldmatrix per-lane address offsets (bytes), within a stage
    const int mat = lane >> 3;     // 0..3
    const int rim = lane & 7;      // row in 8x8 matrix
    uint32_t aOff[4], bOff[4];
#pragma unroll
    for (int mt = 0; mt < 4; mt++)  // A m16 tile: row += (mat&1)*8, kw += (mat>>1)*4
        aOff[mt] = (uint32_t)(((wm + mt * 16 + (mat & 1) * 8 + rim) * SW
                               + (mat >> 1) * 4) * 4);
#pragma unroll
    for (int p = 0; p < 4; p++)     // B nt-pair: row += (mat>>1)*8, kw += (mat&1)*4
        bOff[p] = (uint32_t)((TILE_W + (wn + p * 16 + (mat >> 1) * 8 + rim) * SW
                               + (mat & 1) * 4) * 4);

    float acc[4][8][4];
#pragma unroll
    for (int i = 0; i < 4; i++)
#pragma unroll
        for (int j = 0; j < 8; j++)
#pragma unroll
            for (int q = 0; q < 4; q++) acc[i][j][q] = 0.0f;

    const int KT = K >> 5;   // K / 32

    // per stage: A tile 128 rows x 4 16B-chunks = 512, B same; 1024 chunks /
    // 128 threads = 8 per thread (4 A + 4 B).
    auto issue = [&](int slot, int kt) {
        const uint32_t sa = sm0 + (slot * 2 * TILE_W) * 4;
        const uint32_t sb = sa + TILE_W * 4;
        const int kb = kt * 32;
#pragma unroll
        for (int t = 0; t < 4; t++) {
            int idx = tid + t * 128;          // 0..511
            int r = idx >> 2, c = idx & 3;    // row, 16B-chunk
            cp16(sa + (r * SW + c * 4) * 4, A + (size_t)(row0 + r) * lda + kb + c * 8);
            cp16(sb + (r * SW + c * 4) * 4, B + (size_t)(col0 + r) * ldb + kb + c * 8);
        }
    };

    // prologue: 3 stages in flight
    issue(0, 0); cp_commit();
    issue(1, 1); cp_commit();
    issue(2, 2); cp_commit();

    for (int kt = 0; kt < KT; kt++) {
        asm volatile("cp.async.wait_group 2;" ::: "memory");
        __syncthreads();
        // slot (kt+3)&3 == (kt-1)&3: all warps finished kt-1 before the sync.
        if (kt + 3 < KT) issue((kt + 3) & 3, kt + 3);
        cp_commit();

        const uint32_t stg = sm0 + ((kt & 3) * 2 * TILE_W) * 4;

#pragma unroll
        for (int ks = 0; ks < 2; ks++) {            // two k16 steps per k32
            const uint32_t kb = stg + ks * 32;      // ks*8 words = 32 bytes
            uint32_t af[4][4], bq[4][4];
#pragma unroll
            for (int mt = 0; mt < 4; mt++) ldmx4(af[mt], kb + aOff[mt]);
#pragma unroll
            for (int p = 0; p < 4; p++)    ldmx4(bq[p], kb + bOff[p]);
#pragma unroll
            for (int mt = 0; mt < 4; mt++)
#pragma unroll
                for (int nt = 0; nt < 8; nt++)
                    mma_f16(acc[mt][nt], af[mt], &bq[nt >> 1][(nt & 1) * 2]);
        }
    }

    // Epilogue: c0/c1 at (row, 2*tig), c2/c3 at (row+8, 2*tig)
#pragma unroll
    for (int mt = 0; mt < 4; mt++) {
        const int r = row0 + wm + mt * 16 + gid;
        float inv0 = 1.0f, inv1 = 1.0f;
        if (DIV) { inv0 = 1.0f / rsum[r]; inv1 = 1.0f / rsum[r + 8]; }
        float s0 = 0.0f, s1 = 0.0f;
#pragma unroll
        for (int nt = 0; nt < 8; nt++) {
            const int c = col0 + wn + nt * 8 + 2 * tig;
            float o0 = acc[mt][nt][0] * scale, o1 = acc[mt][nt][1] * scale;
            float o2 = acc[mt][nt][2] * scale, o3 = acc[mt][nt][3] * scale;
            if (EPI == 2) {
                o0 = __expf(o0); o1 = __expf(o1);
                o2 = __expf(o2); o3 = __expf(o3);
            }
            if (EPI == 0) {
                float* C = (float*)Cv;
                if (DIV) { o0 *= inv0; o1 *= inv0; o2 *= inv1; o3 *= inv1; }
                *(float2*)(C + (size_t)r * ldc + c)       = make_float2(o0, o1);
                *(float2*)(C + (size_t)(r + 8) * ldc + c) = make_float2(o2, o3);
            } else {
                __half* C = (__half*)Cv;
                __half2 h0 = __floats2half2_rn(o0, o1);
                __half2 h1 = __floats2half2_rn(o2, o3);
                *(__half2*)(C + (size_t)r * ldc + c)       = h0;
                *(__half2*)(C + (size_t)(r + 8) * ldc + c) = h1;
                if (EPI == 2) {   // accumulate rounded row-sums
                    float2 f0 = __half22float2(h0), f1 = __half22float2(h1);
                    s0 += f0.x + f0.y;
                    s1 += f1.x + f1.y;
                }
            }
        }
        if (EPI == 2) {
            // quad reduce (lanes of same gid: xor 1, 2)
            s0 += __shfl_xor_sync(0xffffffffu, s0, 1);
            s0 += __shfl_xor_sync(0xffffffffu, s0, 2);
            s1 += __shfl_xor_sync(0xffffffffu, s1, 1);
            s1 += __shfl_xor_sync(0xffffffffu, s1, 2);
            if (tig == 0) {
                atomicAdd(rsum + r, s0);
                atomicAdd(rsum + r + 8, s1);
            }
        }
    }
}

// ---------------------------------------------------------------------------
extern "C" void kernel_launch(void* const* d_in, const int* in_sizes, int n_in,
                              void* d_out, int out_size)
{
    const float* x  = (const float*)d_in[0];
    const float* Wq = (const float*)d_in[1];
    const float* Wk = (const float*)d_in[2];
    const float* Wv = (const float*)d_in[3];
    float* out = (float*)d_out;

    __half *xh, *wqkh, *wvh, *qkh, *vth, *ph;
    float *rsp;
    cudaGetSymbolAddress((void**)&xh,   g_xh);
    cudaGetSymbolAddress((void**)&wqkh, g_wqkh);
    cudaGetSymbolAddress((void**)&wvh,  g_wvh);
    cudaGetSymbolAddress((void**)&qkh,  g_qkh);
    cudaGetSymbolAddress((void**)&vth,  g_vth);
    cudaGetSymbolAddress((void**)&ph,   g_ph);
    cudaGetSymbolAddress((void**)&rsp,  g_rsum);

    cudaFuncSetAttribute((const void*)gemm_h<1, false>,
                         cudaFuncAttributeMaxDynamicSharedMemorySize, SMEM_BYTES);
    cudaFuncSetAttribute((const void*)gemm_h<2, false>,
                         cudaFuncAttributeMaxDynamicSharedMemorySize, SMEM_BYTES);
    cudaFuncSetAttribute((const void*)gemm_h<0, true>,
                         cudaFuncAttributeMaxDynamicSharedMemorySize, SMEM_BYTES);

    const float scale = 1.0f / 32.0f;  // 1/sqrt(1024)

    // fp32 -> fp16 (one launch) + rsum zero (deterministic for graph replay)
    cvt_all<<<(XN4 + 3 * WN4 + 255) / 256, 256>>>(x, Wq, Wk, Wv, xh, wqkh, wvh);
    zero_rsum<<<SEQ / 256, 256>>>(rsp);

    // [Q|K] = X @ [Wq;Wk]^T   [4096, 2048] fp16
    gemm_h<1, false><<<dim3(2 * DIM / 128, SEQ / 128), 128, SMEM_BYTES>>>(
        xh, wqkh, qkh, DIM, DIM, DIM, 2 * DIM, 1.0f, nullptr);

    // V^T = Wv @ X^T   [1024, 4096] fp16
    gemm_h<1, false><<<dim3(SEQ / 128, DIM / 128), 128, SMEM_BYTES>>>(
        wvh, xh, vth, DIM, DIM, DIM, SEQ, 1.0f, nullptr);

    // P = exp((Q @ K^T) / 32)  fp16 (unnormalized) + rowsum atomics
    gemm_h<2, false><<<dim3(SEQ / 128, SEQ / 128), 128, SMEM_BYTES>>>(
        qkh, qkh + DIM, ph, DIM, 2 * DIM, 2 * DIM, SEQ, scale, rsp);

    // O = (P @ (V^T)^T) / rowsum   [4096, 1024] fp32
    gemm_h<0, true><<<dim3(DIM / 128, SEQ / 128), 128, SMEM_BYTES>>>(
        ph, vth, out, SEQ, SEQ, SEQ, DIM, 1.0f, rsp);
}